// round 14
// baseline (speedup 1.0000x reference)
#include <cuda_runtime.h>
#include <cuda_bf16.h>
#include <cuda_fp16.h>
#include <cstdint>
#include <cstdio>
#include <math.h>

// Problem constants (fixed shapes)
static const int NW = 200000;
static const int NT = 100000;
static const int EMAX = 500000;

// ---------------- device scratch (static globals; no allocations allowed) ----
__device__ __align__(16) float  g_fw[(size_t)NW * 128];   // wallet features
__device__ __align__(16) float  g_ft[(size_t)NT * 128];   // token features
__device__ __align__(16) __half g_hw[(size_t)NW * 256];   // wallet hs: [hs_wt | hs_ww] (fp16)
__device__ __align__(16) __half g_ht[(size_t)NT * 128];   // token hs:  [hs_tw] (fp16)
__device__ __align__(16) float  g_aw[(size_t)NW * 8];     // wallet a: [as_wt, ad_tw, as_ww, ad_ww] x2 heads
__device__ __align__(16) float  g_at[(size_t)NT * 4];     // token a:  [ad_wt, as_tw] x2 heads
__device__ __align__(16) float  g_vw[2 * 128 * 8];        // folded att vectors (wallet)
__device__ __align__(16) float  g_vt[2 * 128 * 4];        // folded att vectors (token)
__device__ int   g_rp0[NT + 1];            // CSR rowptr, dst=token  (e_wt)
__device__ int   g_rp1[NW + 1];            // dst=wallet (e_tw)
__device__ int   g_rp2[NW + 1];            // dst=wallet (e_ww)
__device__ int   g_ei0[EMAX];
__device__ int   g_ei1[EMAX];
__device__ int   g_ei2[EMAX];
__device__ int   g_deg[NT + 2 * NW];       // per-type degree (offsets 0 / NT / NT+NW)
__device__ int   g_cur[NT + 2 * NW];       // fill cursors
__device__ int   g_part3[3 * 256];         // scan partials per type
__device__ int   g_is64;                   // edge dtype flag (1 = int64, 0 = int32)

// ---------------- streams/events for forked graph capture (host-side only) ---
struct AsyncCtx {
    cudaStream_t s1 = nullptr, s2 = nullptr;
    cudaEvent_t  ev[16] = {};
    bool ok = false;
    AsyncCtx() {
        if (cudaStreamCreateWithFlags(&s1, cudaStreamNonBlocking) != cudaSuccess) return;
        if (cudaStreamCreateWithFlags(&s2, cudaStreamNonBlocking) != cudaSuccess) return;
        for (int i = 0; i < 16; i++)
            if (cudaEventCreateWithFlags(&ev[i], cudaEventDisableTiming) != cudaSuccess) return;
        ok = true;
    }
};
static AsyncCtx g_async;

// ---------------- edge dtype detection ----------------
__global__ void detect_dtype_kernel(const void* e)
{
    if (threadIdx.x == 0 && blockIdx.x == 0) {
        const int* p = (const int*)e;
        int is64 = 1;
        for (int i = 0; i < 16; i++)
            if (p[2 * i + 1] != 0) is64 = 0;
        g_is64 = is64;
    }
}

__device__ __forceinline__ int edge_id(const void* e, int idx)
{
    return g_is64 ? (int)((const long long*)e)[idx] : ((const int*)e)[idx];
}

// ---------------- vatt: fold attention vectors through projection weights ----
__global__ void vatt_kernel(const float* Ws0, const float* Wd0, const float* as0, const float* ad0,
                            const float* Ws1, const float* Wd1, const float* as1, const float* ad1,
                            float* vw, float* vt)
{
    int b = blockIdx.x;
    int l = b / 12, j = b % 12;
    int K = l ? 128 : 64;
    const float* Wsrc = l ? Ws1 : Ws0;
    const float* Wdst = l ? Wd1 : Wd0;
    const float* atts = l ? as1 : as0;
    const float* attd = l ? ad1 : ad0;
    int k = threadIdx.x;
    if (k >= K) return;

    int wallet, slot, h;
    if (j < 8) { wallet = 1; slot = j >> 1; h = j & 1; }
    else       { wallet = 0; slot = (j - 8) >> 1; h = (j - 8) & 1; }

    int type, use_src;
    if (wallet) {
        const int types[4] = {0, 1, 2, 2};   // as_wt, ad_tw, as_ww, ad_ww
        const int srcs[4]  = {1, 0, 1, 0};
        type = types[slot]; use_src = srcs[slot];
    } else {
        const int types[2] = {0, 1};         // ad_wt, as_tw
        const int srcs[2]  = {0, 1};
        type = types[slot]; use_src = srcs[slot];
    }
    const float* W   = (use_src ? Wsrc : Wdst) + (size_t)type * K * 128;
    const float* att = (use_src ? atts : attd) + type * 128 + h * 64;

    float sum = 0.f;
    for (int c = 0; c < 64; c++)
        sum += W[(size_t)k * 128 + h * 64 + c] * att[c];

    if (wallet) vw[l * 128 * 8 + k * 8 + slot * 2 + h] = sum;
    else        vt[l * 128 * 4 + k * 4 + slot * 2 + h] = sum;
}

// ---------------- fused CSR build (3 edge types via blockIdx.y) ----------
__global__ void zero_deg_kernel(int* p, int n)
{
    int i = blockIdx.x * blockDim.x + threadIdx.x;
    if (i < n) p[i] = 0;
}

__global__ void count3_kernel(const void* e0, const void* e1, const void* e2,
                              int E, int* __restrict__ deg)
{
    int t = blockIdx.y;
    int i = blockIdx.x * blockDim.x + threadIdx.x;
    if (i >= E) return;
    const void* e = t == 0 ? e0 : (t == 1 ? e1 : e2);
    int n   = t == 0 ? NT : NW;
    int off = t == 0 ? 0 : (t == 1 ? NT : NT + NW);
    int d = edge_id(e, E + i);
    if ((unsigned)d < (unsigned)n) atomicAdd(&deg[off + d], 1);
}

__global__ void scan3_block_kernel(const int* __restrict__ deg,
                                   int* __restrict__ rp0, int* __restrict__ rp1, int* __restrict__ rp2,
                                   int* __restrict__ part)
{
    __shared__ int sh[1024];
    int t = blockIdx.y;
    int n   = t == 0 ? NT : NW;
    int off = t == 0 ? 0 : (t == 1 ? NT : NT + NW);
    int* out = t == 0 ? rp0 : (t == 1 ? rp1 : rp2);
    int tid = threadIdx.x;
    int gid = blockIdx.x * 1024 + tid;
    int v = (gid < n) ? deg[off + gid] : 0;
    sh[tid] = v; __syncthreads();
    for (int o = 1; o < 1024; o <<= 1) {
        int tmp = (tid >= o) ? sh[tid - o] : 0;
        __syncthreads();
        sh[tid] += tmp;
        __syncthreads();
    }
    if (gid < n) out[gid] = sh[tid] - v;   // exclusive
    if (tid == 1023) part[t * 256 + blockIdx.x] = sh[1023];
}

__global__ void scan3_part_kernel(int* part)
{
    __shared__ int sh[256];
    int t = blockIdx.x;
    int n = (t == 0) ? NT : NW;
    int nb = (n + 1023) / 1024;
    int tid = threadIdx.x;
    int v = (tid < nb) ? part[t * 256 + tid] : 0;
    sh[tid] = v; __syncthreads();
    for (int o = 1; o < 256; o <<= 1) {
        int tmp = (tid >= o) ? sh[tid - o] : 0;
        __syncthreads();
        sh[tid] += tmp;
        __syncthreads();
    }
    if (tid < nb) part[t * 256 + tid] = sh[tid] - v; // exclusive
}

__global__ void addoff3_kernel(int* __restrict__ rp0, int* __restrict__ rp1, int* __restrict__ rp2,
                               const int* __restrict__ part, int* __restrict__ cur, int E)
{
    int t = blockIdx.y;
    int n   = t == 0 ? NT : NW;
    int off = t == 0 ? 0 : (t == 1 ? NT : NT + NW);
    int* rp = t == 0 ? rp0 : (t == 1 ? rp1 : rp2);
    int i = blockIdx.x * blockDim.x + threadIdx.x;
    if (i < n) {
        int v = rp[i] + part[t * 256 + (i >> 10)];
        rp[i] = v;
        cur[off + i] = v;
    }
    if (i == 0) rp[n] = E;
}

__global__ void fill3_kernel(const void* e0, const void* e1, const void* e2, int E,
                             int* __restrict__ cur,
                             int* __restrict__ ei0, int* __restrict__ ei1, int* __restrict__ ei2)
{
    int t = blockIdx.y;
    int i = blockIdx.x * blockDim.x + threadIdx.x;
    if (i >= E) return;
    const void* e = t == 0 ? e0 : (t == 1 ? e1 : e2);
    int n   = t == 0 ? NT : NW;
    int off = t == 0 ? 0 : (t == 1 ? NT : NT + NW);
    int* ei = t == 0 ? ei0 : (t == 1 ? ei1 : ei2);
    int d = edge_id(e, E + i);
    int s = edge_id(e, i);
    if ((unsigned)d < (unsigned)n) {
        int pos = atomicAdd(&cur[off + d], 1);
        if ((unsigned)pos < (unsigned)E) ei[pos] = s;
    }
}

// ---------------- bf16x3 helpers --------------------------------------------
__device__ __forceinline__ uint32_t pk_bf16(float a, float b)
{
    __nv_bfloat162 t = __floats2bfloat162_rn(a, b);
    return *reinterpret_cast<uint32_t*>(&t);
}

__device__ __forceinline__ float bf_res(float x)   // x - bf16(x)
{
    return x - __bfloat162float(__float2bfloat16(x));
}

__device__ __forceinline__ void mma_bf16(float c[4], const uint32_t a[4], const uint32_t b[2])
{
    asm volatile(
        "mma.sync.aligned.m16n8k16.row.col.f32.bf16.bf16.f32 "
        "{%0,%1,%2,%3}, {%4,%5,%6,%7}, {%8,%9}, {%0,%1,%2,%3};\n"
        : "+f"(c[0]), "+f"(c[1]), "+f"(c[2]), "+f"(c[3])
        : "r"(a[0]), "r"(a[1]), "r"(a[2]), "r"(a[3]), "r"(b[0]), "r"(b[1]));
}

__device__ __forceinline__ void store2(float* p, float a, float b)
{
    *(float2*)p = make_float2(a, b);
}
__device__ __forceinline__ void store2(__half* p, float a, float b)
{
    *(__half2*)p = __floats2half2_rn(a, b);
}

// ---------------- single-B GEMM (R12 version, non-pipelined) ----------------
template<int BN, typename OT, int NS>
__global__ void __launch_bounds__(BN * 4) gemm_kernel(
    const float* __restrict__ A, int lda,
    const float* __restrict__ B, int ldb,
    OT* __restrict__ C, int ldc,
    int M, int K, const float* __restrict__ bias,
    const float* __restrict__ vatt, float* __restrict__ aout)
{
    const int T = BN * 4;
    __shared__ uint32_t Ah[16][137], Al[16][137];
    __shared__ uint32_t Bh[16][BN + 8], Bl[16][BN + 8];
    int tid = threadIdx.x;
    int r0 = blockIdx.x * 128;
    int c0 = blockIdx.y * BN;
    int wid = tid >> 5, lane = tid & 31;
    int wm = (wid & 3) * 32;
    int wn = (wid >> 2) * 32;
    int gID = lane >> 2, tig = lane & 3;

    float acc[2][4][4];
    #pragma unroll
    for (int mi = 0; mi < 2; mi++)
        #pragma unroll
        for (int ni = 0; ni < 4; ni++)
            #pragma unroll
            for (int q = 0; q < 4; q++) acc[mi][ni][q] = 0.f;

    float areg[NS > 0 ? NS : 1];
    if (NS > 0)
        #pragma unroll
        for (int s = 0; s < NS; s++) areg[s] = 0.f;

    for (int k0 = 0; k0 < K; k0 += 32) {
        #pragma unroll
        for (int i = 0; i < 1024 / T; i++) {
            int id = tid + i * T;
            int r = id >> 3, q = id & 7;
            float4 v = make_float4(0.f, 0.f, 0.f, 0.f);
            int gr = r0 + r;
            if (gr < M) v = *(const float4*)&A[(size_t)gr * lda + k0 + q * 4];
            Ah[2 * q][r]     = pk_bf16(v.x, v.y);
            Al[2 * q][r]     = pk_bf16(bf_res(v.x), bf_res(v.y));
            Ah[2 * q + 1][r] = pk_bf16(v.z, v.w);
            Al[2 * q + 1][r] = pk_bf16(bf_res(v.z), bf_res(v.w));
        }
        {
            int kp = tid / (BN / 4), nq = tid % (BN / 4);
            const float* bp = &B[(size_t)(k0 + 2 * kp) * ldb + c0 + nq * 4];
            float4 u = *(const float4*)bp;
            float4 w = *(const float4*)(bp + ldb);
            Bh[kp][4 * nq + 0] = pk_bf16(u.x, w.x);
            Bl[kp][4 * nq + 0] = pk_bf16(bf_res(u.x), bf_res(w.x));
            Bh[kp][4 * nq + 1] = pk_bf16(u.y, w.y);
            Bl[kp][4 * nq + 1] = pk_bf16(bf_res(u.y), bf_res(w.y));
            Bh[kp][4 * nq + 2] = pk_bf16(u.z, w.z);
            Bl[kp][4 * nq + 2] = pk_bf16(bf_res(u.z), bf_res(w.z));
            Bh[kp][4 * nq + 3] = pk_bf16(u.w, w.w);
            Bl[kp][4 * nq + 3] = pk_bf16(bf_res(u.w), bf_res(w.w));
        }
        __syncthreads();

        if (NS > 0) {
            int r = tid >> 2, q = tid & 3;
            #pragma unroll
            for (int kp = 0; kp < 4; kp++) {
                int kpp = q * 4 + kp;
                uint32_t hi = Ah[kpp][r], lo = Al[kpp][r];
                float a0 = __uint_as_float(hi << 16) + __uint_as_float(lo << 16);
                float a1 = __uint_as_float(hi & 0xffff0000u) + __uint_as_float(lo & 0xffff0000u);
                const float* vp = vatt + (size_t)(k0 + 2 * kpp) * NS;
                #pragma unroll
                for (int s = 0; s < NS; s++)
                    areg[s] += a0 * vp[s] + a1 * vp[s + NS];
            }
        }

        #pragma unroll
        for (int s = 0; s < 2; s++) {
            int kb = s * 8;
            uint32_t ah[2][4], al[2][4];
            #pragma unroll
            for (int mi = 0; mi < 2; mi++) {
                int m0 = wm + mi * 16 + gID;
                ah[mi][0] = Ah[kb + tig][m0];     al[mi][0] = Al[kb + tig][m0];
                ah[mi][1] = Ah[kb + tig][m0 + 8]; al[mi][1] = Al[kb + tig][m0 + 8];
                ah[mi][2] = Ah[kb + tig + 4][m0];     al[mi][2] = Al[kb + tig + 4][m0];
                ah[mi][3] = Ah[kb + tig + 4][m0 + 8]; al[mi][3] = Al[kb + tig + 4][m0 + 8];
            }
            uint32_t bh[4][2], bl[4][2];
            #pragma unroll
            for (int ni = 0; ni < 4; ni++) {
                int n0 = wn + ni * 8 + gID;
                bh[ni][0] = Bh[kb + tig][n0];     bl[ni][0] = Bl[kb + tig][n0];
                bh[ni][1] = Bh[kb + tig + 4][n0]; bl[ni][1] = Bl[kb + tig + 4][n0];
            }
            #pragma unroll
            for (int mi = 0; mi < 2; mi++)
                #pragma unroll
                for (int ni = 0; ni < 4; ni++) {
                    mma_bf16(acc[mi][ni], ah[mi], bl[ni]);
                    mma_bf16(acc[mi][ni], al[mi], bh[ni]);
                    mma_bf16(acc[mi][ni], ah[mi], bh[ni]);
                }
        }
        __syncthreads();
    }

    if (NS > 0) {
        #pragma unroll
        for (int s = 0; s < NS; s++) {
            areg[s] += __shfl_xor_sync(0xffffffffu, areg[s], 1);
            areg[s] += __shfl_xor_sync(0xffffffffu, areg[s], 2);
        }
        int row = r0 + (tid >> 2);
        if ((tid & 3) == 0 && row < M) {
            #pragma unroll
            for (int s = 0; s < NS; s++)
                aout[(size_t)row * NS + s] = areg[s];
        }
    }

    #pragma unroll
    for (int mi = 0; mi < 2; mi++) {
        #pragma unroll
        for (int ni = 0; ni < 4; ni++) {
            int row = r0 + wm + mi * 16 + gID;
            int col = c0 + wn + ni * 8 + 2 * tig;
            float bv0 = bias ? bias[col] : 0.f;
            float bv1 = bias ? bias[col + 1] : 0.f;
            if (row < M)
                store2(&C[(size_t)row * ldc + col], acc[mi][ni][0] + bv0, acc[mi][ni][1] + bv1);
            if (row + 8 < M)
                store2(&C[(size_t)(row + 8) * ldc + col], acc[mi][ni][2] + bv0, acc[mi][ni][3] + bv1);
        }
    }
}

// ---------------- dual-B GEMM: C[:,0:128]=A@B0, C[:,128:256]=A@B1 ----------
// BM=64, 256 threads, 8 warps (2 along M x 4 along N). A staged ONCE.
// NS>0: fused attention scalars (4 lanes/row x 64 rows = 256 threads).
template<int NS>
__global__ void __launch_bounds__(256) gemm_dual_kernel(
    const float* __restrict__ A, int lda,
    const float* __restrict__ B0, const float* __restrict__ B1, int ldb,
    __half* __restrict__ C, int ldc,   // ldc = 256; out0 at col 0, out1 at col 128
    int M, int K,
    const float* __restrict__ vatt, float* __restrict__ aout)
{
    __shared__ uint32_t Ah[16][72], Al[16][72];
    __shared__ uint32_t Bh[2][16][136], Bl[2][16][136];
    int tid = threadIdx.x;
    int r0 = blockIdx.x * 64;
    int wid = tid >> 5, lane = tid & 31;
    int wm = (wid & 1) * 32;           // 2 warps along M
    int wn = (wid >> 1) * 32;          // 4 warps along N
    int gID = lane >> 2, tig = lane & 3;

    float acc[2][2][4][4];             // [output][mi][ni][quad]
    #pragma unroll
    for (int o = 0; o < 2; o++)
        #pragma unroll
        for (int mi = 0; mi < 2; mi++)
            #pragma unroll
            for (int ni = 0; ni < 4; ni++)
                #pragma unroll
                for (int q = 0; q < 4; q++) acc[o][mi][ni][q] = 0.f;

    float areg[NS > 0 ? NS : 1];
    if (NS > 0)
        #pragma unroll
        for (int s = 0; s < NS; s++) areg[s] = 0.f;

    for (int k0 = 0; k0 < K; k0 += 32) {
        // stage A: 64 rows x 32 k = 512 float4 items, 2 per thread
        #pragma unroll
        for (int i = 0; i < 2; i++) {
            int id = tid + i * 256;
            int r = id >> 3, q = id & 7;
            float4 v = make_float4(0.f, 0.f, 0.f, 0.f);
            int gr = r0 + r;
            if (gr < M) v = *(const float4*)&A[(size_t)gr * lda + k0 + q * 4];
            Ah[2 * q][r]     = pk_bf16(v.x, v.y);
            Al[2 * q][r]     = pk_bf16(bf_res(v.x), bf_res(v.y));
            Ah[2 * q + 1][r] = pk_bf16(v.z, v.w);
            Al[2 * q + 1][r] = pk_bf16(bf_res(v.z), bf_res(v.w));
        }
        // stage B0/B1: 16 kp x 32 nq = 512 items each, 2 per thread per matrix
        #pragma unroll
        for (int o = 0; o < 2; o++) {
            const float* Bm = o ? B1 : B0;
            #pragma unroll
            for (int i = 0; i < 2; i++) {
                int id = tid + i * 256;
                int kp = id >> 5, nq = id & 31;
                const float* bp = &Bm[(size_t)(k0 + 2 * kp) * ldb + nq * 4];
                float4 u = *(const float4*)bp;
                float4 w = *(const float4*)(bp + ldb);
                Bh[o][kp][4 * nq + 0] = pk_bf16(u.x, w.x);
                Bl[o][kp][4 * nq + 0] = pk_bf16(bf_res(u.x), bf_res(w.x));
                Bh[o][kp][4 * nq + 1] = pk_bf16(u.y, w.y);
                Bl[o][kp][4 * nq + 1] = pk_bf16(bf_res(u.y), bf_res(w.y));
                Bh[o][kp][4 * nq + 2] = pk_bf16(u.z, w.z);
                Bl[o][kp][4 * nq + 2] = pk_bf16(bf_res(u.z), bf_res(w.z));
                Bh[o][kp][4 * nq + 3] = pk_bf16(u.w, w.w);
                Bl[o][kp][4 * nq + 3] = pk_bf16(bf_res(u.w), bf_res(w.w));
            }
        }
        __syncthreads();

        // fused attention scalars (4 lanes per row, rows 0..63)
        if (NS > 0) {
            int r = tid >> 2, q = tid & 3;
            #pragma unroll
            for (int kp = 0; kp < 4; kp++) {
                int kpp = q * 4 + kp;
                uint32_t hi = Ah[kpp][r], lo = Al[kpp][r];
                float a0 = __uint_as_float(hi << 16) + __uint_as_float(lo << 16);
                float a1 = __uint_as_float(hi & 0xffff0000u) + __uint_as_float(lo & 0xffff0000u);
                const float* vp = vatt + (size_t)(k0 + 2 * kpp) * NS;
                #pragma unroll
                for (int s = 0; s < NS; s++)
                    areg[s] += a0 * vp[s] + a1 * vp[s + NS];
            }
        }

        #pragma unroll
        for (int s = 0; s < 2; s++) {
            int kb = s * 8;
            uint32_t ah[2][4], al[2][4];
            #pragma unroll
            for (int mi = 0; mi < 2; mi++) {
                int m0 = wm + mi * 16 + gID;
                ah[mi][0] = Ah[kb + tig][m0];     al[mi][0] = Al[kb + tig][m0];
                ah[mi][1] = Ah[kb + tig][m0 + 8]; al[mi][1] = Al[kb + tig][m0 + 8];
                ah[mi][2] = Ah[kb + tig + 4][m0];     al[mi][2] = Al[kb + tig + 4][m0];
                ah[mi][3] = Ah[kb + tig + 4][m0 + 8]; al[mi][3] = Al[kb + tig + 4][m0 + 8];
            }
            #pragma unroll
            for (int o = 0; o < 2; o++) {
                uint32_t bh[4][2], bl[4][2];
                #pragma unroll
                for (int ni = 0; ni < 4; ni++) {
                    int n0 = wn + ni * 8 + gID;
                    bh[ni][0] = Bh[o][kb + tig][n0];     bl[ni][0] = Bl[o][kb + tig][n0];
                    bh[ni][1] = Bh[o][kb + tig + 4][n0]; bl[ni][1] = Bl[o][kb + tig + 4][n0];
                }
                #pragma unroll
                for (int mi = 0; mi < 2; mi++)
                    #pragma unroll
                    for (int ni = 0; ni < 4; ni++) {
                        mma_bf16(acc[o][mi][ni], ah[mi], bl[ni]);
                        mma_bf16(acc[o][mi][ni], al[mi], bh[ni]);
                        mma_bf16(acc[o][mi][ni], ah[mi], bh[ni]);
                    }
            }
        }
        __syncthreads();
    }

    if (NS > 0) {
        #pragma unroll
        for (int s = 0; s < NS; s++) {
            areg[s] += __shfl_xor_sync(0xffffffffu, areg[s], 1);
            areg[s] += __shfl_xor_sync(0xffffffffu, areg[s], 2);
        }
        int row = r0 + (tid >> 2);
        if ((tid & 3) == 0 && row < M) {
            #pragma unroll
            for (int s = 0; s < NS; s++)
                aout[(size_t)row * NS + s] = areg[s];
        }
    }

    #pragma unroll
    for (int o = 0; o < 2; o++) {
        #pragma unroll
        for (int mi = 0; mi < 2; mi++) {
            #pragma unroll
            for (int ni = 0; ni < 4; ni++) {
                int row = r0 + wm + mi * 16 + gID;
                int col = o * 128 + wn + ni * 8 + 2 * tig;
                if (row < M)
                    store2(&C[(size_t)row * ldc + col], acc[o][mi][ni][0], acc[o][mi][ni][1]);
                if (row + 8 < M)
                    store2(&C[(size_t)(row + 8) * ldc + col], acc[o][mi][ni][2], acc[o][mi][ni][3]);
            }
        }
    }
}

// ---------------- single GAT conv accumulation (shfl-broadcast, smem-free) --
__device__ __forceinline__ float4 conv_acc(
    const int* __restrict__ rp, const int* __restrict__ ei,
    const float* __restrict__ as_, int sa,
    float ad0, float ad1,
    const __half* __restrict__ hs, int sh,
    int w, int lane, int h)
{
    float4 acc = make_float4(0.f, 0.f, 0.f, 0.f);
    int beg = rp[w], end = rp[w + 1];
    int deg = end - beg;
    if (deg <= 0) return acc;

    if (deg <= 32) {
        int ee = beg + lane;
        int src = 0;
        float x0 = -1e30f, x1 = -1e30f;
        if (ee < end) {
            src = ei[ee];
            float2 a2 = *(const float2*)&as_[(size_t)src * sa];
            x0 = a2.x + ad0;
            x1 = a2.y + ad1;
            x0 = x0 > 0.f ? x0 : 0.2f * x0;
            x1 = x1 > 0.f ? x1 : 0.2f * x1;
        }
        float m0 = x0, m1 = x1;
        #pragma unroll
        for (int o = 16; o; o >>= 1) {
            m0 = fmaxf(m0, __shfl_xor_sync(0xffffffffu, m0, o));
            m1 = fmaxf(m1, __shfl_xor_sync(0xffffffffu, m1, o));
        }
        float w0 = (ee < end) ? __expf(x0 - m0) : 0.f;
        float w1 = (ee < end) ? __expf(x1 - m1) : 0.f;
        float s0 = w0, s1 = w1;
        #pragma unroll
        for (int o = 16; o; o >>= 1) {
            s0 += __shfl_xor_sync(0xffffffffu, s0, o);
            s1 += __shfl_xor_sync(0xffffffffu, s1, o);
        }
        float wn0 = w0 * (1.f / (s0 + 1e-16f));
        float wn1 = w1 * (1.f / (s1 + 1e-16f));
        for (int j = 0; j < deg; j++) {
            int s   = __shfl_sync(0xffffffffu, src, j);
            float a = __shfl_sync(0xffffffffu, wn0, j);
            float b = __shfl_sync(0xffffffffu, wn1, j);
            float wt = h ? b : a;
            uint2 u = *(const uint2*)&hs[(size_t)s * sh + lane * 4];
            float2 f0 = __half22float2(*(const __half2*)&u.x);
            float2 f1 = __half22float2(*(const __half2*)&u.y);
            acc.x += wt * f0.x; acc.y += wt * f0.y;
            acc.z += wt * f1.x; acc.w += wt * f1.y;
        }
        return acc;
    }

    // general path: online softmax across chunks (rare)
    float m0 = -1e30f, m1 = -1e30f;
    float s0 = 0.f, s1 = 0.f;
    for (int e0 = beg; e0 < end; e0 += 32) {
        int ee = e0 + lane;
        int cnt = min(32, end - e0);
        float x0 = -1e30f, x1 = -1e30f;
        int src = 0;
        if (ee < end) {
            src = ei[ee];
            float2 a2 = *(const float2*)&as_[(size_t)src * sa];
            x0 = a2.x + ad0;
            x1 = a2.y + ad1;
            x0 = x0 > 0.f ? x0 : 0.2f * x0;
            x1 = x1 > 0.f ? x1 : 0.2f * x1;
        }
        float cm0 = x0, cm1 = x1;
        #pragma unroll
        for (int o = 16; o; o >>= 1) {
            cm0 = fmaxf(cm0, __shfl_xor_sync(0xffffffffu, cm0, o));
            cm1 = fmaxf(cm1, __shfl_xor_sync(0xffffffffu, cm1, o));
        }
        float nm0 = fmaxf(m0, cm0), nm1 = fmaxf(m1, cm1);
        float r0 = __expf(m0 - nm0), r1 = __expf(m1 - nm1);
        float w0 = (ee < end) ? __expf(x0 - nm0) : 0.f;
        float w1 = (ee < end) ? __expf(x1 - nm1) : 0.f;
        float cs0 = w0, cs1 = w1;
        #pragma unroll
        for (int o = 16; o; o >>= 1) {
            cs0 += __shfl_xor_sync(0xffffffffu, cs0, o);
            cs1 += __shfl_xor_sync(0xffffffffu, cs1, o);
        }
        s0 = s0 * r0 + cs0;
        s1 = s1 * r1 + cs1;
        float rh = h ? r1 : r0;
        acc.x *= rh; acc.y *= rh; acc.z *= rh; acc.w *= rh;
        m0 = nm0; m1 = nm1;

        for (int j = 0; j < cnt; j++) {
            int s   = __shfl_sync(0xffffffffu, src, j);
            float a = __shfl_sync(0xffffffffu, w0, j);
            float b = __shfl_sync(0xffffffffu, w1, j);
            float wt = h ? b : a;
            uint2 u = *(const uint2*)&hs[(size_t)s * sh + lane * 4];
            float2 f0 = __half22float2(*(const __half2*)&u.x);
            float2 f1 = __half22float2(*(const __half2*)&u.y);
            acc.x += wt * f0.x; acc.y += wt * f0.y;
            acc.z += wt * f1.x; acc.w += wt * f1.y;
        }
    }
    float invh = 1.f / ((h ? s1 : s0) + 1e-16f);
    acc.x *= invh; acc.y *= invh; acc.z *= invh; acc.w *= invh;
    return acc;
}

__device__ __forceinline__ void finalize_store(
    float4 acc, float* __restrict__ out, int w, int lane,
    const float* __restrict__ bias1, const float* __restrict__ bias2,
    const float* __restrict__ clsW, const float* __restrict__ clsb,
    float* __restrict__ logits, int logit_off, int do_cls)
{
    int c = lane * 4;
    float r[4] = {acc.x, acc.y, acc.z, acc.w};
    #pragma unroll
    for (int j = 0; j < 4; j++) {
        float v = r[j] + bias1[c + j] + (bias2 ? bias2[c + j] : 0.f);
        r[j] = v > 0.f ? v : (__expf(v) - 1.f);
    }
    if (!do_cls) {
        *(float4*)&out[(size_t)w * 128 + c] = make_float4(r[0], r[1], r[2], r[3]);
        return;
    }
    float4 wa = *(const float4*)&clsW[c * 2];
    float4 wb = *(const float4*)&clsW[c * 2 + 4];
    float p0 = r[0] * wa.x + r[1] * wa.z + r[2] * wb.x + r[3] * wb.z;
    float p1 = r[0] * wa.y + r[1] * wa.w + r[2] * wb.y + r[3] * wb.w;
    #pragma unroll
    for (int o = 16; o; o >>= 1) {
        p0 += __shfl_xor_sync(0xffffffffu, p0, o);
        p1 += __shfl_xor_sync(0xffffffffu, p1, o);
    }
    if (lane == 0) {
        logits[(size_t)(logit_off + w) * 2]     = p0 + clsb[0];
        logits[(size_t)(logit_off + w) * 2 + 1] = p1 + clsb[1];
    }
}

// ---------------- token conv: single edge type, finalize ------------------
__global__ __launch_bounds__(256) void gat_conv1_kernel(
    const int* __restrict__ rp, const int* __restrict__ ei,
    const float* __restrict__ as_, int sa,
    const float* __restrict__ ad_, int sd,
    const __half* __restrict__ hs, int sh,
    float* __restrict__ out, int ndst,
    const float* __restrict__ bias1,
    const float* __restrict__ clsW, const float* __restrict__ clsb,
    float* __restrict__ logits, int logit_off, int do_cls)
{
    int w = (blockIdx.x * blockDim.x + threadIdx.x) >> 5;
    int lane = threadIdx.x & 31;
    if (w >= ndst) return;
    int h = lane >> 4;

    float ad0 = ad_[(size_t)w * sd];
    float ad1 = ad_[(size_t)w * sd + 1];
    float4 acc = conv_acc(rp, ei, as_, sa, ad0, ad1, hs, sh, w, lane, h);
    finalize_store(acc, out, w, lane, bias1, nullptr, clsW, clsb, logits, logit_off, do_cls);
}

// ---------------- wallet conv: two edge types merged, finalize -------------
__global__ __launch_bounds__(256) void gat_conv2_kernel(
    const int* __restrict__ rpA, const int* __restrict__ eiA,
    const float* __restrict__ asA, int saA,
    const __half* __restrict__ hsA, int shA,
    const int* __restrict__ rpB, const int* __restrict__ eiB,
    const float* __restrict__ asB, int saB,
    const __half* __restrict__ hsB, int shB,
    const float* __restrict__ aw,
    float* __restrict__ out, int ndst,
    const float* __restrict__ bias1, const float* __restrict__ bias2,
    const float* __restrict__ clsW, const float* __restrict__ clsb,
    float* __restrict__ logits, int do_cls)
{
    int w = (blockIdx.x * blockDim.x + threadIdx.x) >> 5;
    int lane = threadIdx.x & 31;
    if (w >= ndst) return;
    int h = lane >> 4;

    float4 adv = *(const float4*)&aw[(size_t)w * 8 + 4];   // {as_ww0, as_ww1, ad_ww0, ad_ww1}
    float2 adt = *(const float2*)&aw[(size_t)w * 8 + 2];   // {ad_tw0, ad_tw1}

    float4 a1 = conv_acc(rpA, eiA, asA, saA, adt.x, adt.y, hsA, shA, w, lane, h);
    float4 a2 = conv_acc(rpB, eiB, asB, saB, adv.z, adv.w, hsB, shB, w, lane, h);
    a1.x += a2.x; a1.y += a2.y; a1.z += a2.z; a1.w += a2.w;

    finalize_store(a1, out, w, lane, bias1, bias2, clsW, clsb, logits, 0, do_cls);
}

// ---------------- host orchestration ----------------
extern "C" void kernel_launch(void* const* d_in, const int* in_sizes, int n_in,
                              void* d_out, int out_size)
{
    const float* x_wallet = (const float*)d_in[0];
    const float* x_token  = (const float*)d_in[1];
    const float* lin_w_W  = (const float*)d_in[2];
    const float* lin_w_b  = (const float*)d_in[3];
    const float* lin_t_W  = (const float*)d_in[4];
    const float* lin_t_b  = (const float*)d_in[5];
    const float* Wsrc0    = (const float*)d_in[6];
    const float* Wdst0    = (const float*)d_in[7];
    const float* atts0    = (const float*)d_in[8];
    const float* attd0    = (const float*)d_in[9];
    const float* b0       = (const float*)d_in[10];
    const float* Wsrc1    = (const float*)d_in[11];
    const float* Wdst1    = (const float*)d_in[12];
    const float* atts1    = (const float*)d_in[13];
    const float* attd1    = (const float*)d_in[14];
    const float* b1       = (const float*)d_in[15];
    const float* cls_w_W  = (const float*)d_in[16];
    const float* cls_w_b  = (const float*)d_in[17];
    const float* cls_t_W  = (const float*)d_in[18];
    const float* cls_t_b  = (const float*)d_in[19];
    const void* e_wt = d_in[20];
    const void* e_tw = d_in[21];
    const void* e_ww = d_in[22];
    int E = in_sizes[20] / 2;

    float *fw, *ft, *aw, *at, *vw, *vt;
    __half *hw, *ht;
    int *rp0, *rp1, *rp2, *ei0, *ei1, *ei2, *deg, *cur, *part;
    cudaGetSymbolAddress((void**)&fw, g_fw);
    cudaGetSymbolAddress((void**)&ft, g_ft);
    cudaGetSymbolAddress((void**)&hw, g_hw);
    cudaGetSymbolAddress((void**)&ht, g_ht);
    cudaGetSymbolAddress((void**)&aw, g_aw);
    cudaGetSymbolAddress((void**)&at, g_at);
    cudaGetSymbolAddress((void**)&vw, g_vw);
    cudaGetSymbolAddress((void**)&vt, g_vt);
    cudaGetSymbolAddress((void**)&rp0, g_rp0);
    cudaGetSymbolAddress((void**)&rp1, g_rp1);
    cudaGetSymbolAddress((void**)&rp2, g_rp2);
    cudaGetSymbolAddress((void**)&ei0, g_ei0);
    cudaGetSymbolAddress((void**)&ei1, g_ei1);
    cudaGetSymbolAddress((void**)&ei2, g_ei2);
    cudaGetSymbolAddress((void**)&deg, g_deg);
    cudaGetSymbolAddress((void**)&cur, g_cur);
    cudaGetSymbolAddress((void**)&part, g_part3);

    bool fork = g_async.ok;
    cudaStream_t s1 = fork ? g_async.s1 : 0;
    cudaStream_t s2 = fork ? g_async.s2 : 0;
    #define REC(i, st)  do { if (fork) cudaEventRecord(g_async.ev[i], st); } while (0)
    #define WAIT(st, i) do { if (fork) cudaStreamWaitEvent(st, g_async.ev[i], 0); } while (0)

    // s0: dtype + vatt + CSR zero
    detect_dtype_kernel<<<1, 32>>>(e_wt);
    vatt_kernel<<<24, 128>>>(Wsrc0, Wdst0, atts0, attd0, Wsrc1, Wdst1, atts1, attd1, vw, vt);
    int ndeg = NT + 2 * NW;
    zero_deg_kernel<<<(ndeg + 255) / 256, 256>>>(deg, ndeg);

    // fork: input projections on s1
    REC(0, 0); WAIT(s1, 0);
    gemm_kernel<64, float, 0><<<dim3((NW + 127) / 128, 1), 256, 0, s1>>>(x_wallet, 128, lin_w_W, 64, fw, 64, NW, 128, lin_w_b, nullptr, nullptr);
    gemm_kernel<64, float, 0><<<dim3((NT + 127) / 128, 1), 256, 0, s1>>>(x_token, 64, lin_t_W, 64, ft, 64, NT, 64, lin_t_b, nullptr, nullptr);

    // s0: CSR build
    count3_kernel<<<dim3((E + 255) / 256, 3), 256>>>(e_wt, e_tw, e_ww, E, deg);
    int nbmax = (NW + 1023) / 1024;
    scan3_block_kernel<<<dim3(nbmax, 3), 1024>>>(deg, rp0, rp1, rp2, part);
    scan3_part_kernel<<<3, 256>>>(part);
    addoff3_kernel<<<dim3((NW + 255) / 256, 3), 256>>>(rp0, rp1, rp2, part, cur, E);
    fill3_kernel<<<dim3((E + 255) / 256, 3), 256>>>(e_wt, e_tw, e_ww, E, cur, ei0, ei1, ei2);

    // join input gemms into s0
    REC(1, s1); WAIT(0, 1);

    int ldf = 64;
    for (int l = 0; l < 2; l++) {
        const float* Wsrc = l ? Wsrc1 : Wsrc0;
        const float* bl = l ? b1 : b0;
        int K = l ? 128 : 64;
        int eb = 2 + l * 6;

        // fork: wallet dual-B hs gemm (A read once) + token hs gemm
        REC(eb + 0, 0); WAIT(s2, eb + 0);
        gemm_dual_kernel<8><<<(NW + 63) / 64, 256>>>(
            fw, ldf, Wsrc + (size_t)0 * K * 128, Wsrc + (size_t)2 * K * 128, 128,
            hw, 256, NW, K, vw + l * 1024, aw);
        gemm_kernel<128, __half, 4><<<dim3((NT + 127) / 128, 1), 512, 0, s2>>>(
            ft, ldf, Wsrc + (size_t)1 * K * 128, 128, ht, 128, NT, K, nullptr, vt + l * 512, at);

        // join: all gemms complete before convs overwrite fw/ft
        REC(eb + 2, s2);
        WAIT(0, eb + 2);

        // convs: token conv on s1, merged wallet conv on s0
        REC(eb + 3, 0); WAIT(s1, eb + 3);
        gat_conv1_kernel<<<(NT * 32 + 255) / 256, 256, 0, s1>>>(
            rp0, ei0, aw + 0, 8, at + 0, 4, hw + 0, 256, ft, NT,
            bl + 0, cls_t_W, cls_t_b, (float*)d_out, NW, l == 1);
        gat_conv2_kernel<<<(NW * 32 + 255) / 256, 256>>>(
            rp1, ei1, at + 2, 4, ht, 128,
            rp2, ei2, aw + 4, 8, hw + 128, 256,
            aw, fw, NW, bl + 128, bl + 256, cls_w_W, cls_w_b, (float*)d_out, l == 1);
        REC(eb + 4, s1); WAIT(0, eb + 4);

        ldf = 128;
    }

    #undef REC
    #undef WAIT
}

// round 15
// speedup vs baseline: 1.0835x; 1.0835x over previous
#include <cuda_runtime.h>
#include <cuda_bf16.h>
#include <cuda_fp16.h>
#include <cstdint>
#include <cstdio>
#include <math.h>

// Problem constants (fixed shapes)
static const int NW = 200000;
static const int NT = 100000;
static const int EMAX = 500000;

// ---------------- device scratch (static globals; no allocations allowed) ----
__device__ __align__(16) __half g_fw[(size_t)NW * 128];   // wallet features (fp16)
__device__ __align__(16) __half g_ft[(size_t)NT * 128];   // token features (fp16)
__device__ __align__(16) __half g_hw[(size_t)NW * 256];   // wallet hs: [hs_wt | hs_ww] (fp16)
__device__ __align__(16) __half g_ht[(size_t)NT * 128];   // token hs:  [hs_tw] (fp16)
__device__ __align__(16) float  g_aw[(size_t)NW * 8];     // wallet a: [as_wt, ad_tw, as_ww, ad_ww] x2 heads
__device__ __align__(16) float  g_at[(size_t)NT * 4];     // token a:  [ad_wt, as_tw] x2 heads
__device__ __align__(16) float  g_vw[2 * 128 * 8];        // folded att vectors (wallet)
__device__ __align__(16) float  g_vt[2 * 128 * 4];        // folded att vectors (token)
__device__ int   g_rp0[NT + 1];            // CSR rowptr, dst=token  (e_wt)
__device__ int   g_rp1[NW + 1];            // dst=wallet (e_tw)
__device__ int   g_rp2[NW + 1];            // dst=wallet (e_ww)
__device__ int   g_ei0[EMAX];
__device__ int   g_ei1[EMAX];
__device__ int   g_ei2[EMAX];
__device__ int   g_deg[NT + 2 * NW];       // per-type degree (offsets 0 / NT / NT+NW)
__device__ int   g_cur[NT + 2 * NW];       // fill cursors
__device__ int   g_part3[3 * 256];         // scan partials per type
__device__ int   g_is64;                   // edge dtype flag (1 = int64, 0 = int32)

// ---------------- streams/events for forked graph capture (host-side only) ---
struct AsyncCtx {
    cudaStream_t s1 = nullptr, s2 = nullptr;
    cudaEvent_t  ev[16] = {};
    bool ok = false;
    AsyncCtx() {
        if (cudaStreamCreateWithFlags(&s1, cudaStreamNonBlocking) != cudaSuccess) return;
        if (cudaStreamCreateWithFlags(&s2, cudaStreamNonBlocking) != cudaSuccess) return;
        for (int i = 0; i < 16; i++)
            if (cudaEventCreateWithFlags(&ev[i], cudaEventDisableTiming) != cudaSuccess) return;
        ok = true;
    }
};
static AsyncCtx g_async;

// ---------------- edge dtype detection ----------------
__global__ void detect_dtype_kernel(const void* e)
{
    if (threadIdx.x == 0 && blockIdx.x == 0) {
        const int* p = (const int*)e;
        int is64 = 1;
        for (int i = 0; i < 16; i++)
            if (p[2 * i + 1] != 0) is64 = 0;
        g_is64 = is64;
    }
}

__device__ __forceinline__ int edge_id(const void* e, int idx)
{
    return g_is64 ? (int)((const long long*)e)[idx] : ((const int*)e)[idx];
}

// ---------------- vatt: fold attention vectors through projection weights ----
__global__ void vatt_kernel(const float* Ws0, const float* Wd0, const float* as0, const float* ad0,
                            const float* Ws1, const float* Wd1, const float* as1, const float* ad1,
                            float* vw, float* vt)
{
    int b = blockIdx.x;
    int l = b / 12, j = b % 12;
    int K = l ? 128 : 64;
    const float* Wsrc = l ? Ws1 : Ws0;
    const float* Wdst = l ? Wd1 : Wd0;
    const float* atts = l ? as1 : as0;
    const float* attd = l ? ad1 : ad0;
    int k = threadIdx.x;
    if (k >= K) return;

    int wallet, slot, h;
    if (j < 8) { wallet = 1; slot = j >> 1; h = j & 1; }
    else       { wallet = 0; slot = (j - 8) >> 1; h = (j - 8) & 1; }

    int type, use_src;
    if (wallet) {
        const int types[4] = {0, 1, 2, 2};   // as_wt, ad_tw, as_ww, ad_ww
        const int srcs[4]  = {1, 0, 1, 0};
        type = types[slot]; use_src = srcs[slot];
    } else {
        const int types[2] = {0, 1};         // ad_wt, as_tw
        const int srcs[2]  = {0, 1};
        type = types[slot]; use_src = srcs[slot];
    }
    const float* W   = (use_src ? Wsrc : Wdst) + (size_t)type * K * 128;
    const float* att = (use_src ? atts : attd) + type * 128 + h * 64;

    float sum = 0.f;
    for (int c = 0; c < 64; c++)
        sum += W[(size_t)k * 128 + h * 64 + c] * att[c];

    if (wallet) vw[l * 128 * 8 + k * 8 + slot * 2 + h] = sum;
    else        vt[l * 128 * 4 + k * 4 + slot * 2 + h] = sum;
}

// ---------------- fused CSR build (3 edge types via blockIdx.y) ----------
__global__ void zero_deg_kernel(int* p, int n)
{
    int i = blockIdx.x * blockDim.x + threadIdx.x;
    if (i < n) p[i] = 0;
}

__global__ void count3_kernel(const void* e0, const void* e1, const void* e2,
                              int E, int* __restrict__ deg)
{
    int t = blockIdx.y;
    int i = blockIdx.x * blockDim.x + threadIdx.x;
    if (i >= E) return;
    const void* e = t == 0 ? e0 : (t == 1 ? e1 : e2);
    int n   = t == 0 ? NT : NW;
    int off = t == 0 ? 0 : (t == 1 ? NT : NT + NW);
    int d = edge_id(e, E + i);
    if ((unsigned)d < (unsigned)n) atomicAdd(&deg[off + d], 1);
}

__global__ void scan3_block_kernel(const int* __restrict__ deg,
                                   int* __restrict__ rp0, int* __restrict__ rp1, int* __restrict__ rp2,
                                   int* __restrict__ part)
{
    __shared__ int sh[1024];
    int t = blockIdx.y;
    int n   = t == 0 ? NT : NW;
    int off = t == 0 ? 0 : (t == 1 ? NT : NT + NW);
    int* out = t == 0 ? rp0 : (t == 1 ? rp1 : rp2);
    int tid = threadIdx.x;
    int gid = blockIdx.x * 1024 + tid;
    int v = (gid < n) ? deg[off + gid] : 0;
    sh[tid] = v; __syncthreads();
    for (int o = 1; o < 1024; o <<= 1) {
        int tmp = (tid >= o) ? sh[tid - o] : 0;
        __syncthreads();
        sh[tid] += tmp;
        __syncthreads();
    }
    if (gid < n) out[gid] = sh[tid] - v;   // exclusive
    if (tid == 1023) part[t * 256 + blockIdx.x] = sh[1023];
}

__global__ void scan3_part_kernel(int* part)
{
    __shared__ int sh[256];
    int t = blockIdx.x;
    int n = (t == 0) ? NT : NW;
    int nb = (n + 1023) / 1024;
    int tid = threadIdx.x;
    int v = (tid < nb) ? part[t * 256 + tid] : 0;
    sh[tid] = v; __syncthreads();
    for (int o = 1; o < 256; o <<= 1) {
        int tmp = (tid >= o) ? sh[tid - o] : 0;
        __syncthreads();
        sh[tid] += tmp;
        __syncthreads();
    }
    if (tid < nb) part[t * 256 + tid] = sh[tid] - v; // exclusive
}

__global__ void addoff3_kernel(int* __restrict__ rp0, int* __restrict__ rp1, int* __restrict__ rp2,
                               const int* __restrict__ part, int* __restrict__ cur, int E)
{
    int t = blockIdx.y;
    int n   = t == 0 ? NT : NW;
    int off = t == 0 ? 0 : (t == 1 ? NT : NT + NW);
    int* rp = t == 0 ? rp0 : (t == 1 ? rp1 : rp2);
    int i = blockIdx.x * blockDim.x + threadIdx.x;
    if (i < n) {
        int v = rp[i] + part[t * 256 + (i >> 10)];
        rp[i] = v;
        cur[off + i] = v;
    }
    if (i == 0) rp[n] = E;
}

__global__ void fill3_kernel(const void* e0, const void* e1, const void* e2, int E,
                             int* __restrict__ cur,
                             int* __restrict__ ei0, int* __restrict__ ei1, int* __restrict__ ei2)
{
    int t = blockIdx.y;
    int i = blockIdx.x * blockDim.x + threadIdx.x;
    if (i >= E) return;
    const void* e = t == 0 ? e0 : (t == 1 ? e1 : e2);
    int n   = t == 0 ? NT : NW;
    int off = t == 0 ? 0 : (t == 1 ? NT : NT + NW);
    int* ei = t == 0 ? ei0 : (t == 1 ? ei1 : ei2);
    int d = edge_id(e, E + i);
    int s = edge_id(e, i);
    if ((unsigned)d < (unsigned)n) {
        int pos = atomicAdd(&cur[off + d], 1);
        if ((unsigned)pos < (unsigned)E) ei[pos] = s;
    }
}

// ---------------- bf16x3 tensor-core GEMM (templated BN/IT/OT/NS) -----------
__device__ __forceinline__ uint32_t pk_bf16(float a, float b)
{
    __nv_bfloat162 t = __floats2bfloat162_rn(a, b);
    return *reinterpret_cast<uint32_t*>(&t);
}

__device__ __forceinline__ float bf_res(float x)   // x - bf16(x)
{
    return x - __bfloat162float(__float2bfloat16(x));
}

__device__ __forceinline__ void mma_bf16(float c[4], const uint32_t a[4], const uint32_t b[2])
{
    asm volatile(
        "mma.sync.aligned.m16n8k16.row.col.f32.bf16.bf16.f32 "
        "{%0,%1,%2,%3}, {%4,%5,%6,%7}, {%8,%9}, {%0,%1,%2,%3};\n"
        : "+f"(c[0]), "+f"(c[1]), "+f"(c[2]), "+f"(c[3])
        : "r"(a[0]), "r"(a[1]), "r"(a[2]), "r"(a[3]), "r"(b[0]), "r"(b[1]));
}

__device__ __forceinline__ void store2(float* p, float a, float b)
{
    *(float2*)p = make_float2(a, b);
}
__device__ __forceinline__ void store2(__half* p, float a, float b)
{
    *(__half2*)p = __floats2half2_rn(a, b);
}

// load 4 consecutive elements as float4
__device__ __forceinline__ float4 ld4(const float* p)  { return *(const float4*)p; }
__device__ __forceinline__ float4 ld4(const __half* p)
{
    uint2 u = *(const uint2*)p;
    float2 f0 = __half22float2(*(const __half2*)&u.x);
    float2 f1 = __half22float2(*(const __half2*)&u.y);
    return make_float4(f0.x, f0.y, f1.x, f1.y);
}

template<int BN, typename IT, typename OT, int NS>
__global__ void __launch_bounds__(BN * 4) gemm_kernel(
    const IT* __restrict__ A, int lda,
    const float* __restrict__ B, int ldb,
    OT* __restrict__ C, int ldc,
    int M, int K, const float* __restrict__ bias,
    const float* __restrict__ vatt, float* __restrict__ aout)
{
    const int T = BN * 4;
    __shared__ uint32_t Ah[16][137], Al[16][137];
    __shared__ uint32_t Bh[16][BN + 8], Bl[16][BN + 8];
    int tid = threadIdx.x;
    int r0 = blockIdx.x * 128;
    int c0 = blockIdx.y * BN;
    int wid = tid >> 5, lane = tid & 31;
    int wm = (wid & 3) * 32;
    int wn = (wid >> 2) * 32;
    int gID = lane >> 2, tig = lane & 3;

    float acc[2][4][4];
    #pragma unroll
    for (int mi = 0; mi < 2; mi++)
        #pragma unroll
        for (int ni = 0; ni < 4; ni++)
            #pragma unroll
            for (int q = 0; q < 4; q++) acc[mi][ni][q] = 0.f;

    float areg[NS > 0 ? NS : 1];
    if (NS > 0)
        #pragma unroll
        for (int s = 0; s < NS; s++) areg[s] = 0.f;

    for (int k0 = 0; k0 < K; k0 += 32) {
        #pragma unroll
        for (int i = 0; i < 1024 / T; i++) {
            int id = tid + i * T;
            int r = id >> 3, q = id & 7;
            float4 v = make_float4(0.f, 0.f, 0.f, 0.f);
            int gr = r0 + r;
            if (gr < M) v = ld4(&A[(size_t)gr * lda + k0 + q * 4]);
            Ah[2 * q][r]     = pk_bf16(v.x, v.y);
            Al[2 * q][r]     = pk_bf16(bf_res(v.x), bf_res(v.y));
            Ah[2 * q + 1][r] = pk_bf16(v.z, v.w);
            Al[2 * q + 1][r] = pk_bf16(bf_res(v.z), bf_res(v.w));
        }
        {
            int kp = tid / (BN / 4), nq = tid % (BN / 4);
            const float* bp = &B[(size_t)(k0 + 2 * kp) * ldb + c0 + nq * 4];
            float4 u = *(const float4*)bp;
            float4 w = *(const float4*)(bp + ldb);
            Bh[kp][4 * nq + 0] = pk_bf16(u.x, w.x);
            Bl[kp][4 * nq + 0] = pk_bf16(bf_res(u.x), bf_res(w.x));
            Bh[kp][4 * nq + 1] = pk_bf16(u.y, w.y);
            Bl[kp][4 * nq + 1] = pk_bf16(bf_res(u.y), bf_res(w.y));
            Bh[kp][4 * nq + 2] = pk_bf16(u.z, w.z);
            Bl[kp][4 * nq + 2] = pk_bf16(bf_res(u.z), bf_res(w.z));
            Bh[kp][4 * nq + 3] = pk_bf16(u.w, w.w);
            Bl[kp][4 * nq + 3] = pk_bf16(bf_res(u.w), bf_res(w.w));
        }
        __syncthreads();

        if (NS > 0) {
            int r = tid >> 2, q = tid & 3;
            #pragma unroll
            for (int kp = 0; kp < 4; kp++) {
                int kpp = q * 4 + kp;
                uint32_t hi = Ah[kpp][r], lo = Al[kpp][r];
                float a0 = __uint_as_float(hi << 16) + __uint_as_float(lo << 16);
                float a1 = __uint_as_float(hi & 0xffff0000u) + __uint_as_float(lo & 0xffff0000u);
                const float* vp = vatt + (size_t)(k0 + 2 * kpp) * NS;
                #pragma unroll
                for (int s = 0; s < NS; s++)
                    areg[s] += a0 * vp[s] + a1 * vp[s + NS];
            }
        }

        #pragma unroll
        for (int s = 0; s < 2; s++) {
            int kb = s * 8;
            uint32_t ah[2][4], al[2][4];
            #pragma unroll
            for (int mi = 0; mi < 2; mi++) {
                int m0 = wm + mi * 16 + gID;
                ah[mi][0] = Ah[kb + tig][m0];     al[mi][0] = Al[kb + tig][m0];
                ah[mi][1] = Ah[kb + tig][m0 + 8]; al[mi][1] = Al[kb + tig][m0 + 8];
                ah[mi][2] = Ah[kb + tig + 4][m0];     al[mi][2] = Al[kb + tig + 4][m0];
                ah[mi][3] = Ah[kb + tig + 4][m0 + 8]; al[mi][3] = Al[kb + tig + 4][m0 + 8];
            }
            uint32_t bh[4][2], bl[4][2];
            #pragma unroll
            for (int ni = 0; ni < 4; ni++) {
                int n0 = wn + ni * 8 + gID;
                bh[ni][0] = Bh[kb + tig][n0];     bl[ni][0] = Bl[kb + tig][n0];
                bh[ni][1] = Bh[kb + tig + 4][n0]; bl[ni][1] = Bl[kb + tig + 4][n0];
            }
            #pragma unroll
            for (int mi = 0; mi < 2; mi++)
                #pragma unroll
                for (int ni = 0; ni < 4; ni++) {
                    mma_bf16(acc[mi][ni], ah[mi], bl[ni]);
                    mma_bf16(acc[mi][ni], al[mi], bh[ni]);
                    mma_bf16(acc[mi][ni], ah[mi], bh[ni]);
                }
        }
        __syncthreads();
    }

    if (NS > 0) {
        #pragma unroll
        for (int s = 0; s < NS; s++) {
            areg[s] += __shfl_xor_sync(0xffffffffu, areg[s], 1);
            areg[s] += __shfl_xor_sync(0xffffffffu, areg[s], 2);
        }
        int row = r0 + (tid >> 2);
        if ((tid & 3) == 0 && row < M) {
            #pragma unroll
            for (int s = 0; s < NS; s++)
                aout[(size_t)row * NS + s] = areg[s];
        }
    }

    #pragma unroll
    for (int mi = 0; mi < 2; mi++) {
        #pragma unroll
        for (int ni = 0; ni < 4; ni++) {
            int row = r0 + wm + mi * 16 + gID;
            int col = c0 + wn + ni * 8 + 2 * tig;
            float bv0 = bias ? bias[col] : 0.f;
            float bv1 = bias ? bias[col + 1] : 0.f;
            if (row < M)
                store2(&C[(size_t)row * ldc + col], acc[mi][ni][0] + bv0, acc[mi][ni][1] + bv1);
            if (row + 8 < M)
                store2(&C[(size_t)(row + 8) * ldc + col], acc[mi][ni][2] + bv0, acc[mi][ni][3] + bv1);
        }
    }
}

// ---------------- single GAT conv accumulation (shfl-broadcast, smem-free) --
__device__ __forceinline__ float4 conv_acc(
    const int* __restrict__ rp, const int* __restrict__ ei,
    const float* __restrict__ as_, int sa,
    float ad0, float ad1,
    const __half* __restrict__ hs, int sh,
    int w, int lane, int h)
{
    float4 acc = make_float4(0.f, 0.f, 0.f, 0.f);
    int beg = rp[w], end = rp[w + 1];
    int deg = end - beg;
    if (deg <= 0) return acc;

    if (deg <= 32) {
        int ee = beg + lane;
        int src = 0;
        float x0 = -1e30f, x1 = -1e30f;
        if (ee < end) {
            src = ei[ee];
            float2 a2 = *(const float2*)&as_[(size_t)src * sa];
            x0 = a2.x + ad0;
            x1 = a2.y + ad1;
            x0 = x0 > 0.f ? x0 : 0.2f * x0;
            x1 = x1 > 0.f ? x1 : 0.2f * x1;
        }
        float m0 = x0, m1 = x1;
        #pragma unroll
        for (int o = 16; o; o >>= 1) {
            m0 = fmaxf(m0, __shfl_xor_sync(0xffffffffu, m0, o));
            m1 = fmaxf(m1, __shfl_xor_sync(0xffffffffu, m1, o));
        }
        float w0 = (ee < end) ? __expf(x0 - m0) : 0.f;
        float w1 = (ee < end) ? __expf(x1 - m1) : 0.f;
        float s0 = w0, s1 = w1;
        #pragma unroll
        for (int o = 16; o; o >>= 1) {
            s0 += __shfl_xor_sync(0xffffffffu, s0, o);
            s1 += __shfl_xor_sync(0xffffffffu, s1, o);
        }
        float wn0 = w0 * (1.f / (s0 + 1e-16f));
        float wn1 = w1 * (1.f / (s1 + 1e-16f));
        for (int j = 0; j < deg; j++) {
            int s   = __shfl_sync(0xffffffffu, src, j);
            float a = __shfl_sync(0xffffffffu, wn0, j);
            float b = __shfl_sync(0xffffffffu, wn1, j);
            float wt = h ? b : a;
            uint2 u = *(const uint2*)&hs[(size_t)s * sh + lane * 4];
            float2 f0 = __half22float2(*(const __half2*)&u.x);
            float2 f1 = __half22float2(*(const __half2*)&u.y);
            acc.x += wt * f0.x; acc.y += wt * f0.y;
            acc.z += wt * f1.x; acc.w += wt * f1.y;
        }
        return acc;
    }

    // general path: online softmax across chunks (rare)
    float m0 = -1e30f, m1 = -1e30f;
    float s0 = 0.f, s1 = 0.f;
    for (int e0 = beg; e0 < end; e0 += 32) {
        int ee = e0 + lane;
        int cnt = min(32, end - e0);
        float x0 = -1e30f, x1 = -1e30f;
        int src = 0;
        if (ee < end) {
            src = ei[ee];
            float2 a2 = *(const float2*)&as_[(size_t)src * sa];
            x0 = a2.x + ad0;
            x1 = a2.y + ad1;
            x0 = x0 > 0.f ? x0 : 0.2f * x0;
            x1 = x1 > 0.f ? x1 : 0.2f * x1;
        }
        float cm0 = x0, cm1 = x1;
        #pragma unroll
        for (int o = 16; o; o >>= 1) {
            cm0 = fmaxf(cm0, __shfl_xor_sync(0xffffffffu, cm0, o));
            cm1 = fmaxf(cm1, __shfl_xor_sync(0xffffffffu, cm1, o));
        }
        float nm0 = fmaxf(m0, cm0), nm1 = fmaxf(m1, cm1);
        float r0 = __expf(m0 - nm0), r1 = __expf(m1 - nm1);
        float w0 = (ee < end) ? __expf(x0 - nm0) : 0.f;
        float w1 = (ee < end) ? __expf(x1 - nm1) : 0.f;
        float cs0 = w0, cs1 = w1;
        #pragma unroll
        for (int o = 16; o; o >>= 1) {
            cs0 += __shfl_xor_sync(0xffffffffu, cs0, o);
            cs1 += __shfl_xor_sync(0xffffffffu, cs1, o);
        }
        s0 = s0 * r0 + cs0;
        s1 = s1 * r1 + cs1;
        float rh = h ? r1 : r0;
        acc.x *= rh; acc.y *= rh; acc.z *= rh; acc.w *= rh;
        m0 = nm0; m1 = nm1;

        for (int j = 0; j < cnt; j++) {
            int s   = __shfl_sync(0xffffffffu, src, j);
            float a = __shfl_sync(0xffffffffu, w0, j);
            float b = __shfl_sync(0xffffffffu, w1, j);
            float wt = h ? b : a;
            uint2 u = *(const uint2*)&hs[(size_t)s * sh + lane * 4];
            float2 f0 = __half22float2(*(const __half2*)&u.x);
            float2 f1 = __half22float2(*(const __half2*)&u.y);
            acc.x += wt * f0.x; acc.y += wt * f0.y;
            acc.z += wt * f1.x; acc.w += wt * f1.y;
        }
    }
    float invh = 1.f / ((h ? s1 : s0) + 1e-16f);
    acc.x *= invh; acc.y *= invh; acc.z *= invh; acc.w *= invh;
    return acc;
}

__device__ __forceinline__ void finalize_store(
    float4 acc, __half* __restrict__ out, int w, int lane,
    const float* __restrict__ bias1, const float* __restrict__ bias2,
    const float* __restrict__ clsW, const float* __restrict__ clsb,
    float* __restrict__ logits, int logit_off, int do_cls)
{
    int c = lane * 4;
    float r[4] = {acc.x, acc.y, acc.z, acc.w};
    #pragma unroll
    for (int j = 0; j < 4; j++) {
        float v = r[j] + bias1[c + j] + (bias2 ? bias2[c + j] : 0.f);
        r[j] = v > 0.f ? v : (__expf(v) - 1.f);
    }
    if (!do_cls) {
        __half2 p0 = __floats2half2_rn(r[0], r[1]);
        __half2 p1 = __floats2half2_rn(r[2], r[3]);
        uint2 st;
        st.x = *reinterpret_cast<uint32_t*>(&p0);
        st.y = *reinterpret_cast<uint32_t*>(&p1);
        *(uint2*)&out[(size_t)w * 128 + c] = st;
        return;
    }
    float4 wa = *(const float4*)&clsW[c * 2];
    float4 wb = *(const float4*)&clsW[c * 2 + 4];
    float p0 = r[0] * wa.x + r[1] * wa.z + r[2] * wb.x + r[3] * wb.z;
    float p1 = r[0] * wa.y + r[1] * wa.w + r[2] * wb.y + r[3] * wb.w;
    #pragma unroll
    for (int o = 16; o; o >>= 1) {
        p0 += __shfl_xor_sync(0xffffffffu, p0, o);
        p1 += __shfl_xor_sync(0xffffffffu, p1, o);
    }
    if (lane == 0) {
        logits[(size_t)(logit_off + w) * 2]     = p0 + clsb[0];
        logits[(size_t)(logit_off + w) * 2 + 1] = p1 + clsb[1];
    }
}

// ---------------- token conv: single edge type, finalize ------------------
__global__ __launch_bounds__(256) void gat_conv1_kernel(
    const int* __restrict__ rp, const int* __restrict__ ei,
    const float* __restrict__ as_, int sa,
    const float* __restrict__ ad_, int sd,
    const __half* __restrict__ hs, int sh,
    __half* __restrict__ out, int ndst,
    const float* __restrict__ bias1,
    const float* __restrict__ clsW, const float* __restrict__ clsb,
    float* __restrict__ logits, int logit_off, int do_cls)
{
    int w = (blockIdx.x * blockDim.x + threadIdx.x) >> 5;
    int lane = threadIdx.x & 31;
    if (w >= ndst) return;
    int h = lane >> 4;

    float ad0 = ad_[(size_t)w * sd];
    float ad1 = ad_[(size_t)w * sd + 1];
    float4 acc = conv_acc(rp, ei, as_, sa, ad0, ad1, hs, sh, w, lane, h);
    finalize_store(acc, out, w, lane, bias1, nullptr, clsW, clsb, logits, logit_off, do_cls);
}

// ---------------- wallet conv: two edge types merged, finalize -------------
__global__ __launch_bounds__(256) void gat_conv2_kernel(
    const int* __restrict__ rpA, const int* __restrict__ eiA,
    const float* __restrict__ asA, int saA,
    const __half* __restrict__ hsA, int shA,
    const int* __restrict__ rpB, const int* __restrict__ eiB,
    const float* __restrict__ asB, int saB,
    const __half* __restrict__ hsB, int shB,
    const float* __restrict__ aw,
    __half* __restrict__ out, int ndst,
    const float* __restrict__ bias1, const float* __restrict__ bias2,
    const float* __restrict__ clsW, const float* __restrict__ clsb,
    float* __restrict__ logits, int do_cls)
{
    int w = (blockIdx.x * blockDim.x + threadIdx.x) >> 5;
    int lane = threadIdx.x & 31;
    if (w >= ndst) return;
    int h = lane >> 4;

    float4 adv = *(const float4*)&aw[(size_t)w * 8 + 4];   // {as_ww0, as_ww1, ad_ww0, ad_ww1}
    float2 adt = *(const float2*)&aw[(size_t)w * 8 + 2];   // {ad_tw0, ad_tw1}

    float4 a1 = conv_acc(rpA, eiA, asA, saA, adt.x, adt.y, hsA, shA, w, lane, h);
    float4 a2 = conv_acc(rpB, eiB, asB, saB, adv.z, adv.w, hsB, shB, w, lane, h);
    a1.x += a2.x; a1.y += a2.y; a1.z += a2.z; a1.w += a2.w;

    finalize_store(a1, out, w, lane, bias1, bias2, clsW, clsb, logits, 0, do_cls);
}

// ---------------- host orchestration ----------------
extern "C" void kernel_launch(void* const* d_in, const int* in_sizes, int n_in,
                              void* d_out, int out_size)
{
    const float* x_wallet = (const float*)d_in[0];
    const float* x_token  = (const float*)d_in[1];
    const float* lin_w_W  = (const float*)d_in[2];
    const float* lin_w_b  = (const float*)d_in[3];
    const float* lin_t_W  = (const float*)d_in[4];
    const float* lin_t_b  = (const float*)d_in[5];
    const float* Wsrc0    = (const float*)d_in[6];
    const float* Wdst0    = (const float*)d_in[7];
    const float* atts0    = (const float*)d_in[8];
    const float* attd0    = (const float*)d_in[9];
    const float* b0       = (const float*)d_in[10];
    const float* Wsrc1    = (const float*)d_in[11];
    const float* Wdst1    = (const float*)d_in[12];
    const float* atts1    = (const float*)d_in[13];
    const float* attd1    = (const float*)d_in[14];
    const float* b1       = (const float*)d_in[15];
    const float* cls_w_W  = (const float*)d_in[16];
    const float* cls_w_b  = (const float*)d_in[17];
    const float* cls_t_W  = (const float*)d_in[18];
    const float* cls_t_b  = (const float*)d_in[19];
    const void* e_wt = d_in[20];
    const void* e_tw = d_in[21];
    const void* e_ww = d_in[22];
    int E = in_sizes[20] / 2;

    float *aw, *at, *vw, *vt;
    __half *fw, *ft, *hw, *ht;
    int *rp0, *rp1, *rp2, *ei0, *ei1, *ei2, *deg, *cur, *part;
    cudaGetSymbolAddress((void**)&fw, g_fw);
    cudaGetSymbolAddress((void**)&ft, g_ft);
    cudaGetSymbolAddress((void**)&hw, g_hw);
    cudaGetSymbolAddress((void**)&ht, g_ht);
    cudaGetSymbolAddress((void**)&aw, g_aw);
    cudaGetSymbolAddress((void**)&at, g_at);
    cudaGetSymbolAddress((void**)&vw, g_vw);
    cudaGetSymbolAddress((void**)&vt, g_vt);
    cudaGetSymbolAddress((void**)&rp0, g_rp0);
    cudaGetSymbolAddress((void**)&rp1, g_rp1);
    cudaGetSymbolAddress((void**)&rp2, g_rp2);
    cudaGetSymbolAddress((void**)&ei0, g_ei0);
    cudaGetSymbolAddress((void**)&ei1, g_ei1);
    cudaGetSymbolAddress((void**)&ei2, g_ei2);
    cudaGetSymbolAddress((void**)&deg, g_deg);
    cudaGetSymbolAddress((void**)&cur, g_cur);
    cudaGetSymbolAddress((void**)&part, g_part3);

    bool fork = g_async.ok;
    cudaStream_t s1 = fork ? g_async.s1 : 0;
    cudaStream_t s2 = fork ? g_async.s2 : 0;
    #define REC(i, st)  do { if (fork) cudaEventRecord(g_async.ev[i], st); } while (0)
    #define WAIT(st, i) do { if (fork) cudaStreamWaitEvent(st, g_async.ev[i], 0); } while (0)

    // s0: dtype + vatt + CSR zero
    detect_dtype_kernel<<<1, 32>>>(e_wt);
    vatt_kernel<<<24, 128>>>(Wsrc0, Wdst0, atts0, attd0, Wsrc1, Wdst1, atts1, attd1, vw, vt);
    int ndeg = NT + 2 * NW;
    zero_deg_kernel<<<(ndeg + 255) / 256, 256>>>(deg, ndeg);

    // fork: input projections on s1 (fp16 feature output)
    REC(0, 0); WAIT(s1, 0);
    gemm_kernel<64, float, __half, 0><<<dim3((NW + 127) / 128, 1), 256, 0, s1>>>(x_wallet, 128, lin_w_W, 64, fw, 64, NW, 128, lin_w_b, nullptr, nullptr);
    gemm_kernel<64, float, __half, 0><<<dim3((NT + 127) / 128, 1), 256, 0, s1>>>(x_token, 64, lin_t_W, 64, ft, 64, NT, 64, lin_t_b, nullptr, nullptr);

    // s0: CSR build
    count3_kernel<<<dim3((E + 255) / 256, 3), 256>>>(e_wt, e_tw, e_ww, E, deg);
    int nbmax = (NW + 1023) / 1024;
    scan3_block_kernel<<<dim3(nbmax, 3), 1024>>>(deg, rp0, rp1, rp2, part);
    scan3_part_kernel<<<3, 256>>>(part);
    addoff3_kernel<<<dim3((NW + 255) / 256, 3), 256>>>(rp0, rp1, rp2, part, cur, E);
    fill3_kernel<<<dim3((E + 255) / 256, 3), 256>>>(e_wt, e_tw, e_ww, E, cur, ei0, ei1, ei2);

    // join input gemms into s0
    REC(1, s1); WAIT(0, 1);

    int ldf = 64;
    for (int l = 0; l < 2; l++) {
        const float* Wsrc = l ? Wsrc1 : Wsrc0;
        const float* bl = l ? b1 : b0;
        int K = l ? 128 : 64;
        int eb = 2 + l * 6;

        // fork: hs projections with fused attention scalars (fp16 A inputs)
        REC(eb + 0, 0); WAIT(s1, eb + 0); WAIT(s2, eb + 0);
        gemm_kernel<128, __half, __half, 8><<<dim3((NW + 127) / 128, 1), 512>>>(
            fw, ldf, Wsrc + (size_t)0 * K * 128, 128, hw + 0, 256, NW, K, nullptr, vw + l * 1024, aw);
        gemm_kernel<128, __half, __half, 0><<<dim3((NW + 127) / 128, 1), 512, 0, s1>>>(
            fw, ldf, Wsrc + (size_t)2 * K * 128, 128, hw + 128, 256, NW, K, nullptr, nullptr, nullptr);
        gemm_kernel<128, __half, __half, 4><<<dim3((NT + 127) / 128, 1), 512, 0, s2>>>(
            ft, ldf, Wsrc + (size_t)1 * K * 128, 128, ht, 128, NT, K, nullptr, vt + l * 512, at);

        // join: all gemms complete before convs overwrite fw/ft
        REC(eb + 1, s1); REC(eb + 2, s2);
        WAIT(0, eb + 1); WAIT(0, eb + 2);

        // convs: token conv on s1, merged wallet conv on s0
        REC(eb + 3, 0); WAIT(s1, eb + 3);
        gat_conv1_kernel<<<(NT * 32 + 255) / 256, 256, 0, s1>>>(
            rp0, ei0, aw + 0, 8, at + 0, 4, hw + 0, 256, ft, NT,
            bl + 0, cls_t_W, cls_t_b, (float*)d_out, NW, l == 1);
        gat_conv2_kernel<<<(NW * 32 + 255) / 256, 256>>>(
            rp1, ei1, at + 2, 4, ht, 128,
            rp2, ei2, aw + 4, 8, hw + 128, 256,
            aw, fw, NW, bl + 128, bl + 256, cls_w_W, cls_w_b, (float*)d_out, l == 1);
        REC(eb + 4, s1); WAIT(0, eb + 4);

        ldf = 128;
    }

    #undef REC
    #undef WAIT
}